// round 5
// baseline (speedup 1.0000x reference)
#include <cuda_runtime.h>
#include <math.h>

// ---------------------------------------------------------------------------
// PrettyPCF fused single-kernel, R5.
//  * 192 i-tiles x 6 j-splits = 1152 blocks, 256 thr, ~12KB smem -> high occ.
//  * Phase A: warp-aggregated (ballot/popc) survivor push, packed u|ii.
//  * Phase B: warps drain queue, lane==bin; warp-UNIFORM skip of the bin
//    half whose Gaussian underflows for this u (u<4.4 -> low half,
//    u>2.1 -> high half); exp2f with per-lane FMA-form argument.
//  * Perimeter weights computed per block with interior early-out (w=1).
//  * Done-counter finalize + state reset (graph-replay deterministic).
// ---------------------------------------------------------------------------

#define NPTS   1536
#define NBINS  50
#define TILE_I 8
#define ITILES (NPTS / TILE_I)    // 192
#define JSPLIT 6
#define JLEN   (NPTS / JSPLIT)    // 256
#define NBLK   (ITILES * JSPLIT)  // 1152
#define NTHR   256
#define NWARP  (NTHR / 32)
#define QCAP   (NTHR * TILE_I)    // 2048 worst-case survivors
#define ZC     1.2f

#define RMAX_D (2.0 * sqrt(1.0 / (2.0 * sqrt(3.0) * 1536.0)))

__device__ float g_acc[NBINS];   // zero-init at load; reset by last block
__device__ int   g_done;

__global__ __launch_bounds__(NTHR)
void pcf_kernel(const float* __restrict__ A, const float* __restrict__ B,
                const int* __restrict__ scp, float* __restrict__ out)
{
    __shared__ float sbx[JLEN];
    __shared__ float sby[JLEN];
    __shared__ float sax[TILE_I], say[TILE_I];
    __shared__ float sw[TILE_I * NBINS];
    __shared__ unsigned qpk[QCAP];
    __shared__ float sacc[NBINS];
    __shared__ int   qcount;
    __shared__ int   is_last;

    const int tid   = threadIdx.x;
    const int lane  = tid & 31;
    const int wid   = tid >> 5;
    const int itile = blockIdx.x / JSPLIT;
    const int jsp   = blockIdx.x - itile * JSPLIT;
    const int i0    = itile * TILE_I;
    const int j0    = jsp * JLEN;

    // ---- Stage inputs ----
    if (tid < TILE_I) {
        sax[tid] = A[3 * (i0 + tid)];
        say[tid] = A[3 * (i0 + tid) + 1];
    }
    if (tid < JLEN) {                       // JLEN == NTHR
        sbx[tid] = B[3 * (j0 + tid)];
        sby[tid] = B[3 * (j0 + tid) + 1];
    }
    if (tid < NBINS) sacc[tid] = 0.0f;
    if (tid == 0) qcount = 0;
    __syncthreads();

    // ---- Perimeter weights for this tile's 8 i-points (400 items) ----
    const float TWO_PI = 6.2831853071795864769f;
    for (int t = tid; t < TILE_I * NBINS; t += NTHR) {
        int ii = t / NBINS;
        int b  = t - ii * NBINS;
        float x = sax[ii], y = say[ii];
        float rs = (float)((b + 1) * (5.0 / 50.0) * RMAX_D);
        float m  = fminf(fminf(x, 1.0f - x), fminf(y, 1.0f - y));
        float wv = 1.0f;
        if (rs > m) {                       // border-affected only
            float full = TWO_PI;
            float ex[4] = { x, 1.0f - x, y, 1.0f - y };
            float ey[4] = { y, y,        x, x        };
#pragma unroll
            for (int e = 0; e < 4; e++) {
                if (rs > ex[e]) {
                    float ratio = fminf(ex[e] / rs, 1.0f);
                    float alpha = acosf(ratio);
                    float a1 = atan2f(ey[e],        ex[e]);
                    float a2 = atan2f(1.0f - ey[e], ex[e]);
                    full -= fminf(alpha, a1) + fminf(alpha, a2);
                }
            }
            float per = fminf(fmaxf(full * (1.0f / TWO_PI), 0.0f), 1.0f);
            wv = fminf(1.0f / fmaxf(per, 1e-9f), 4.0f);
        }
        sw[t] = wv;
    }

    float ax[TILE_I], ay[TILE_I];
#pragma unroll
    for (int ii = 0; ii < TILE_I; ii++) {
        ax[ii] = sax[ii];
        ay[ii] = say[ii];
    }

    const int   same = *scp;
    const float invR = (float)(1.0 / RMAX_D);
    const float dmax = (float)((5.0 + (double)ZC) * RMAX_D);
    const float cut2 = dmax * dmax;

    __syncthreads();   // sw / qcount ready

    // ---- Phase A: distance test, warp-aggregated push ----
    {
        const int   jg = j0 + tid;
        const float bx = sbx[tid], by = sby[tid];
#pragma unroll
        for (int ii = 0; ii < TILE_I; ii++) {
            float dx = ax[ii] - bx;
            float dy = ay[ii] - by;
            float d2 = fmaf(dx, dx, dy * dy);
            bool pred = (d2 < cut2) && !(same && (i0 + ii) == jg);
            unsigned mask = __ballot_sync(0xFFFFFFFFu, pred);
            if (mask) {
                int leader = __ffs(mask) - 1;
                int base;
                if (lane == leader) base = atomicAdd(&qcount, __popc(mask));
                base = __shfl_sync(0xFFFFFFFFu, base, leader);
                if (pred) {
                    int slot = base + __popc(mask & ((1u << lane) - 1u));
                    float u = sqrtf(d2) * invR;   // d/RMAX in [0, 6.2]
                    qpk[slot] = (__float_as_uint(u) & ~0xFu) | (unsigned)ii;
                }
            }
        }
    }
    __syncthreads();

    // ---- Phase B: warps drain queue, lane == bin, uniform half-skip ----
    // exp(-16 z^2), z = 0.1*(bin+1) - u  ->  exp2(c0 + c1*u + c2*u^2)
    const float L2E = 1.4426950408889634f;
    const float c2  = -16.0f * L2E;                       // uniform
    const float zb1 = 0.1f * (float)(lane + 1);           // RS[l]/RMAX
    const float zb2 = zb1 + 3.2f;
    const float c1a = 32.0f * zb1 * L2E;
    const float c0a = -16.0f * zb1 * zb1 * L2E;
    const float c1b = 32.0f * zb2 * L2E;
    const float c0b = -16.0f * zb2 * zb2 * L2E;

    float acc1 = 0.0f, acc2 = 0.0f;
    {
        int nq = qcount;
        for (int e = wid; e < nq; e += NWARP) {
            unsigned pk = qpk[e];                         // LDS broadcast
            int   ii = (int)(pk & 0xFu);
            float u  = __uint_as_float(pk & ~0xFu);       // warp-uniform
            float u2 = u * u;
            const float* wrow = &sw[ii * NBINS];
            if (u < 3.2f + ZC) {          // low half (bins 1..32) alive
                float arg = fmaf(c2, u2, fmaf(c1a, u, c0a));
                acc1 = fmaf(exp2f(arg), wrow[lane], acc1);
            }
            if (u > 3.3f - ZC) {          // high half (bins 33..50) alive
                if (lane < NBINS - 32) {
                    float arg = fmaf(c2, u2, fmaf(c1b, u, c0b));
                    acc2 = fmaf(exp2f(arg), wrow[lane + 32], acc2);
                }
            }
        }
    }

    // ---- Block reduction -> global ----
    atomicAdd(&sacc[lane], acc1);
    if (lane < NBINS - 32) atomicAdd(&sacc[lane + 32], acc2);
    __syncthreads();
    if (tid < NBINS) atomicAdd(&g_acc[tid], sacc[tid]);

    // ---- Last block finalizes ----
    __threadfence();
    if (tid == 0) {
        int v = atomicAdd(&g_done, 1);
        is_last = (v == NBLK - 1);
    }
    __syncthreads();
    if (is_last) {
        if (tid < NBINS) {
            int b = tid;
            double rs_d  = (b + 1) * (5.0 / 50.0) * RMAX_D;
            double inner = fmax(0.0, rs_d - 0.5 * RMAX_D);
            double outer = rs_d + 0.5 * RMAX_D;
            float  area  = (float)(M_PI * (outer * outer - inner * inner));
            const float GF = (float)(1.0 / (sqrt(M_PI) * 0.25));

            float s   = g_acc[b] * GF;
            float pcf = s / 1536.0f / (area * 1536.0f);

            out[2 * b]     = (float)rs_d / (float)RMAX_D;
            out[2 * b + 1] = pcf;

            g_acc[b] = 0.0f;          // reset for next graph replay
        }
        if (tid == 0) g_done = 0;
    }
}

// ---------------------------------------------------------------------------
extern "C" void kernel_launch(void* const* d_in, const int* in_sizes, int n_in,
                              void* d_out, int out_size)
{
    const float* A  = (const float*)d_in[0];   // disks_a [1536,3]
    const float* B  = (const float*)d_in[1];   // disks_b [1536,3]
    const int*   sc = (const int*)d_in[2];     // same_category scalar
    float* out = (float*)d_out;

    pcf_kernel<<<NBLK, NTHR>>>(A, B, sc, out);
}

// round 6
// speedup vs baseline: 1.0827x; 1.0827x over previous
#include <cuda_runtime.h>
#include <math.h>

// ---------------------------------------------------------------------------
// PrettyPCF fused single-kernel, R6 = R4 skeleton + targeted wins.
//  * 192 i-tiles x 3 j-splits = 576 blocks, 256 thr (R4 config, 20.4us).
//  * Phase A: plain shared-atomic survivor push (measured fine in R4).
//  * Phase B: 2-way ILP unroll (restored) + warp-uniform half-skip +
//    exp2f FMA-form arguments (c0[lane] + c1[lane]*u + c2*u^2).
//  * Weights: atan2f hoisted per (ii,edge) into shared; interior early-out.
// ---------------------------------------------------------------------------

#define NPTS   1536
#define NBINS  50
#define TILE_I 8
#define ITILES (NPTS / TILE_I)    // 192
#define JSPLIT 3
#define JLEN   (NPTS / JSPLIT)    // 512
#define NBLK   (ITILES * JSPLIT)  // 576
#define NTHR   256
#define NWARP  (NTHR / 32)
#define NCHUNK (JLEN / NTHR)      // 2
#define QCAP   (NTHR * TILE_I)    // 2048 worst-case survivors per chunk
#define ZC     1.2f

#define RMAX_D (2.0 * sqrt(1.0 / (2.0 * sqrt(3.0) * 1536.0)))

__device__ float g_acc[NBINS];   // zero-init at load; reset by last block
__device__ int   g_done;

__global__ __launch_bounds__(NTHR)
void pcf_kernel(const float* __restrict__ A, const float* __restrict__ B,
                const int* __restrict__ scp, float* __restrict__ out)
{
    __shared__ float sbx[JLEN];
    __shared__ float sby[JLEN];
    __shared__ float sax[TILE_I], say[TILE_I];
    __shared__ float sw[TILE_I * NBINS];
    __shared__ float sex[TILE_I * 4];     // edge distances
    __shared__ float sa1[TILE_I * 4];     // atan2(ey, ex)
    __shared__ float sa2[TILE_I * 4];     // atan2(1-ey, ex)
    __shared__ unsigned qpk[QCAP];
    __shared__ float sacc[NBINS];
    __shared__ int   qcount;
    __shared__ int   is_last;

    const int tid   = threadIdx.x;
    const int lane  = tid & 31;
    const int wid   = tid >> 5;
    const int itile = blockIdx.x / JSPLIT;
    const int jsp   = blockIdx.x - itile * JSPLIT;
    const int i0    = itile * TILE_I;
    const int j0    = jsp * JLEN;

    // ---- Stage inputs ----
    if (tid < TILE_I) {
        sax[tid] = A[3 * (i0 + tid)];
        say[tid] = A[3 * (i0 + tid) + 1];
    }
    for (int j = tid; j < JLEN; j += NTHR) {
        sbx[j] = B[3 * (j0 + j)];
        sby[j] = B[3 * (j0 + j) + 1];
    }
    if (tid < NBINS) sacc[tid] = 0.0f;
    __syncthreads();

    // ---- Hoisted per-(ii,edge) terms: 32 items, one warp in parallel ----
    if (tid < TILE_I * 4) {
        int ii = tid >> 2, e = tid & 3;
        float x = sax[ii], y = say[ii];
        float exv = (e == 0) ? x : (e == 1) ? (1.0f - x) : (e == 2) ? y : (1.0f - y);
        float eyv = (e < 2) ? y : x;
        sex[tid] = exv;
        sa1[tid] = atan2f(eyv,        exv);
        sa2[tid] = atan2f(1.0f - eyv, exv);
    }
    __syncthreads();

    // ---- Perimeter weights: 400 (ii,b) items; interior points skip ----
    const float TWO_PI = 6.2831853071795864769f;
    for (int t = tid; t < TILE_I * NBINS; t += NTHR) {
        int ii = t / NBINS;
        int b  = t - ii * NBINS;
        float rs = (float)((b + 1) * (5.0 / 50.0) * RMAX_D);
        const float* exp_ = &sex[ii * 4];
        float m = fminf(fminf(exp_[0], exp_[1]), fminf(exp_[2], exp_[3]));
        float wv = 1.0f;
        if (rs > m) {
            float full = TWO_PI;
            float inv_rs = __frcp_rn(rs);
#pragma unroll
            for (int e = 0; e < 4; e++) {
                float exv = exp_[e];
                if (rs > exv) {
                    float alpha = acosf(fminf(exv * inv_rs, 1.0f));
                    full -= fminf(alpha, sa1[ii * 4 + e])
                          + fminf(alpha, sa2[ii * 4 + e]);
                }
            }
            float per = fminf(fmaxf(full * (1.0f / TWO_PI), 0.0f), 1.0f);
            wv = fminf(1.0f / fmaxf(per, 1e-9f), 4.0f);
        }
        sw[t] = wv;
    }

    float ax[TILE_I], ay[TILE_I];
#pragma unroll
    for (int ii = 0; ii < TILE_I; ii++) {
        ax[ii] = sax[ii];
        ay[ii] = say[ii];
    }

    const int   same = *scp;
    const float invR = (float)(1.0 / RMAX_D);
    const float dmax = (float)((5.0 + (double)ZC) * RMAX_D);
    const float cut2 = dmax * dmax;

    // Per-lane exp2 coefficients: exp(-16 z^2), z = zb - u
    //   = exp2(c0 + c1*u + c2*u^2)
    const float L2E = 1.4426950408889634f;
    const float c2  = -16.0f * L2E;
    const float zb1 = 0.1f * (float)(lane + 1);   // bins 0..31
    const float zb2 = zb1 + 3.2f;                 // bins 32..49 (lane<18)
    const float c1a = 32.0f * zb1 * L2E;
    const float c0a = -16.0f * zb1 * zb1 * L2E;
    const float c1b = 32.0f * zb2 * L2E;
    const float c0b = -16.0f * zb2 * zb2 * L2E;

    float acc1 = 0.0f, acc2 = 0.0f;

    __syncthreads();   // sw ready

    for (int chunk = 0; chunk < NCHUNK; chunk++) {
        if (tid == 0) qcount = 0;
        __syncthreads();

        // ---- Phase A: distance test, push survivors (packed u|ii) ----
        int   jl = chunk * NTHR + tid;
        int   jg = j0 + jl;
        float bx = sbx[jl], by = sby[jl];
#pragma unroll
        for (int ii = 0; ii < TILE_I; ii++) {
            float dx = ax[ii] - bx;
            float dy = ay[ii] - by;
            float d2 = fmaf(dx, dx, dy * dy);
            if (d2 < cut2 && !(same && (i0 + ii) == jg)) {
                int slot = atomicAdd(&qcount, 1);
                float u = sqrtf(d2) * invR;         // d/RMAX in [0, 6.2]
                qpk[slot] = (__float_as_uint(u) & ~0xFu) | (unsigned)ii;
            }
        }
        __syncthreads();

        // ---- Phase B: warps drain queue, lane==bin, 2-way ILP, half-skip ----
        int nq = qcount;
        int e  = wid;
        for (; e + NWARP < nq; e += 2 * NWARP) {
            unsigned pkA = qpk[e];
            unsigned pkB = qpk[e + NWARP];
            int   iiA = (int)(pkA & 0xFu);
            int   iiB = (int)(pkB & 0xFu);
            float uA  = __uint_as_float(pkA & ~0xFu);   // warp-uniform
            float uB  = __uint_as_float(pkB & ~0xFu);
            float uA2 = uA * uA;
            float uB2 = uB * uB;
            const float* wrA = &sw[iiA * NBINS];
            const float* wrB = &sw[iiB * NBINS];
            if (uA < 3.2f + ZC) {
                float arg = fmaf(c2, uA2, fmaf(c1a, uA, c0a));
                acc1 = fmaf(exp2f(arg), wrA[lane], acc1);
            }
            if (uB < 3.2f + ZC) {
                float arg = fmaf(c2, uB2, fmaf(c1a, uB, c0a));
                acc1 = fmaf(exp2f(arg), wrB[lane], acc1);
            }
            if (lane < NBINS - 32) {
                if (uA > 3.3f - ZC) {
                    float arg = fmaf(c2, uA2, fmaf(c1b, uA, c0b));
                    acc2 = fmaf(exp2f(arg), wrA[lane + 32], acc2);
                }
                if (uB > 3.3f - ZC) {
                    float arg = fmaf(c2, uB2, fmaf(c1b, uB, c0b));
                    acc2 = fmaf(exp2f(arg), wrB[lane + 32], acc2);
                }
            }
        }
        if (e < nq) {
            unsigned pk = qpk[e];
            int   ii = (int)(pk & 0xFu);
            float u  = __uint_as_float(pk & ~0xFu);
            float u2 = u * u;
            const float* wr = &sw[ii * NBINS];
            if (u < 3.2f + ZC) {
                float arg = fmaf(c2, u2, fmaf(c1a, u, c0a));
                acc1 = fmaf(exp2f(arg), wr[lane], acc1);
            }
            if (lane < NBINS - 32 && u > 3.3f - ZC) {
                float arg = fmaf(c2, u2, fmaf(c1b, u, c0b));
                acc2 = fmaf(exp2f(arg), wr[lane + 32], acc2);
            }
        }
        __syncthreads();   // protect qcount/qpk reuse
    }

    // ---- Block reduction -> global ----
    atomicAdd(&sacc[lane], acc1);
    if (lane < NBINS - 32) atomicAdd(&sacc[lane + 32], acc2);
    __syncthreads();
    if (tid < NBINS) atomicAdd(&g_acc[tid], sacc[tid]);

    // ---- Last block finalizes ----
    __threadfence();
    if (tid == 0) {
        int v = atomicAdd(&g_done, 1);
        is_last = (v == NBLK - 1);
    }
    __syncthreads();
    if (is_last) {
        if (tid < NBINS) {
            int b = tid;
            double rs_d  = (b + 1) * (5.0 / 50.0) * RMAX_D;
            double inner = fmax(0.0, rs_d - 0.5 * RMAX_D);
            double outer = rs_d + 0.5 * RMAX_D;
            float  area  = (float)(M_PI * (outer * outer - inner * inner));
            const float GF = (float)(1.0 / (sqrt(M_PI) * 0.25));

            float s   = g_acc[b] * GF;
            float pcf = s / 1536.0f / (area * 1536.0f);

            out[2 * b]     = (float)rs_d / (float)RMAX_D;
            out[2 * b + 1] = pcf;

            g_acc[b] = 0.0f;          // reset for next graph replay
        }
        if (tid == 0) g_done = 0;
    }
}

// ---------------------------------------------------------------------------
extern "C" void kernel_launch(void* const* d_in, const int* in_sizes, int n_in,
                              void* d_out, int out_size)
{
    const float* A  = (const float*)d_in[0];   // disks_a [1536,3]
    const float* B  = (const float*)d_in[1];   // disks_b [1536,3]
    const int*   sc = (const int*)d_in[2];     // same_category scalar
    float* out = (float*)d_out;

    pcf_kernel<<<NBLK, NTHR>>>(A, B, sc, out);
}

// round 7
// speedup vs baseline: 1.1047x; 1.0203x over previous
#include <cuda_runtime.h>
#include <math.h>

// ---------------------------------------------------------------------------
// PrettyPCF, R7: warp-per-i, queue-free.
//  * Each warp owns one i-point and a 384-long j-slice. Lanes test 32 j's
//    (lane=j), ballot survivors, bit-scan + shfl-broadcast each survivor's
//    u to the warp; lane==bin accumulation into registers.
//  * Perimeter weights live in REGISTERS (lane l: bins l, l+32), computed
//    once per warp-task; edge atan2f pairs done by lanes 0-3 + shfl.
//  * No shared queue, no qcount atomics, no chunk barriers, no weight LDS.
//  * 192 i-tiles x 4 j-splits x 8 warps/block = 768 blocks, ~41 warps/SM.
// ---------------------------------------------------------------------------

#define NPTS   1536
#define NBINS  50
#define WPB    8                   // warps (== i-points) per block
#define NTHR   (WPB * 32)          // 256
#define ITILES (NPTS / WPB)        // 192
#define JSPLIT 4
#define JLEN   (NPTS / JSPLIT)     // 384
#define JITERS (JLEN / 32)         // 12
#define NBLK   (ITILES * JSPLIT)   // 768
#define ZC     1.2f

#define RMAX_D (2.0 * sqrt(1.0 / (2.0 * sqrt(3.0) * 1536.0)))

__device__ float g_acc[NBINS];   // zero-init at load; reset by last block
__device__ int   g_done;

__global__ __launch_bounds__(NTHR)
void pcf_kernel(const float* __restrict__ A, const float* __restrict__ B,
                const int* __restrict__ scp, float* __restrict__ out)
{
    __shared__ float sbx[JLEN];
    __shared__ float sby[JLEN];
    __shared__ float sacc[NBINS];
    __shared__ int   is_last;

    const int tid   = threadIdx.x;
    const int lane  = tid & 31;
    const int wid   = tid >> 5;
    const int itile = blockIdx.x % ITILES;
    const int jsp   = blockIdx.x / ITILES;
    const int i0    = itile * WPB;
    const int j0    = jsp * JLEN;
    const int i     = i0 + wid;          // this warp's i-point

    // ---- Stage this block's B slice ----
    for (int t = tid; t < JLEN; t += NTHR) {
        sbx[t] = B[3 * (j0 + t)];
        sby[t] = B[3 * (j0 + t) + 1];
    }
    if (tid < NBINS) sacc[tid] = 0.0f;

    // ---- This warp's i coords (broadcast LDG) ----
    const float ax = A[3 * i];
    const float ay = A[3 * i + 1];

    // ---- Edge terms: lanes 0-3 compute, shfl-broadcast ----
    const float TWO_PI = 6.2831853071795864769f;
    float exv = 0.0f, a1v = 0.0f, a2v = 0.0f;
    if (lane < 4) {
        int e = lane;
        float ex_ = (e == 0) ? ax : (e == 1) ? (1.0f - ax)
                  : (e == 2) ? ay : (1.0f - ay);
        float ey_ = (e < 2) ? ay : ax;
        exv = ex_;
        a1v = atan2f(ey_,        ex_);
        a2v = atan2f(1.0f - ey_, ex_);
    }
    const float ex0 = __shfl_sync(0xFFFFFFFFu, exv, 0);
    const float ex1 = __shfl_sync(0xFFFFFFFFu, exv, 1);
    const float ex2 = __shfl_sync(0xFFFFFFFFu, exv, 2);
    const float ex3 = __shfl_sync(0xFFFFFFFFu, exv, 3);
    const float a10 = __shfl_sync(0xFFFFFFFFu, a1v, 0);
    const float a11 = __shfl_sync(0xFFFFFFFFu, a1v, 1);
    const float a12 = __shfl_sync(0xFFFFFFFFu, a1v, 2);
    const float a13 = __shfl_sync(0xFFFFFFFFu, a1v, 3);
    const float a20 = __shfl_sync(0xFFFFFFFFu, a2v, 0);
    const float a21 = __shfl_sync(0xFFFFFFFFu, a2v, 1);
    const float a22 = __shfl_sync(0xFFFFFFFFu, a2v, 2);
    const float a23 = __shfl_sync(0xFFFFFFFFu, a2v, 3);
    const float mEdge = fminf(fminf(ex0, ex1), fminf(ex2, ex3));

    // ---- Per-lane weights for bins lane (rs1) and lane+32 (rs2) ----
    const float rs1 = (float)((lane +  1) * (5.0 / 50.0) * RMAX_D);
    const float rs2 = (float)((lane + 33) * (5.0 / 50.0) * RMAX_D);

    float w1, w2;
    {
        float wv = 1.0f;
        if (rs1 > mEdge) {
            float full = TWO_PI;
            if (rs1 > ex0) { float al = acosf(fminf(ex0 / rs1, 1.0f)); full -= fminf(al, a10) + fminf(al, a20); }
            if (rs1 > ex1) { float al = acosf(fminf(ex1 / rs1, 1.0f)); full -= fminf(al, a11) + fminf(al, a21); }
            if (rs1 > ex2) { float al = acosf(fminf(ex2 / rs1, 1.0f)); full -= fminf(al, a12) + fminf(al, a22); }
            if (rs1 > ex3) { float al = acosf(fminf(ex3 / rs1, 1.0f)); full -= fminf(al, a13) + fminf(al, a23); }
            float per = fminf(fmaxf(full * (1.0f / TWO_PI), 0.0f), 1.0f);
            wv = fminf(1.0f / fmaxf(per, 1e-9f), 4.0f);
        }
        w1 = wv;
    }
    if (lane < NBINS - 32) {
        float wv = 1.0f;
        if (rs2 > mEdge) {
            float full = TWO_PI;
            if (rs2 > ex0) { float al = acosf(fminf(ex0 / rs2, 1.0f)); full -= fminf(al, a10) + fminf(al, a20); }
            if (rs2 > ex1) { float al = acosf(fminf(ex1 / rs2, 1.0f)); full -= fminf(al, a11) + fminf(al, a21); }
            if (rs2 > ex2) { float al = acosf(fminf(ex2 / rs2, 1.0f)); full -= fminf(al, a12) + fminf(al, a22); }
            if (rs2 > ex3) { float al = acosf(fminf(ex3 / rs2, 1.0f)); full -= fminf(al, a13) + fminf(al, a23); }
            float per = fminf(fmaxf(full * (1.0f / TWO_PI), 0.0f), 1.0f);
            wv = fminf(1.0f / fmaxf(per, 1e-9f), 4.0f);
        }
        w2 = wv;
    } else {
        w2 = 0.0f;    // dead bins: contribute 0 branchlessly
    }

    // ---- exp2 coefficients: exp(-16 (zb-u)^2) = exp2(c0 + c1 u + c2 u^2) ----
    const float L2E = 1.4426950408889634f;
    const float c2  = -16.0f * L2E;
    const float zb1 = 0.1f * (float)(lane + 1);
    const float zb2 = zb1 + 3.2f;
    const float c1a = 32.0f * zb1 * L2E;
    const float c0a = -16.0f * zb1 * zb1 * L2E;
    const float c1b = 32.0f * zb2 * L2E;
    const float c0b = -16.0f * zb2 * zb2 * L2E;

    const int   same = *scp;
    const float invR = (float)(1.0 / RMAX_D);
    const float dmax = (float)((5.0 + (double)ZC) * RMAX_D);
    const float cut2 = dmax * dmax;

    float acc1 = 0.0f, acc2 = 0.0f;

    __syncthreads();   // sbx/sby + sacc ready

    // ---- Main loop: lanes test 32 j's; shfl-broadcast survivors ----
    for (int jt = 0; jt < JITERS; jt++) {
        int   jl = jt * 32 + lane;
        float bx = sbx[jl], by = sby[jl];
        float dx = ax - bx;
        float dy = ay - by;
        float d2 = fmaf(dx, dx, dy * dy);
        bool pred = (d2 < cut2) && !(same && i == (j0 + jl));
        float u = sqrtf(d2) * invR;                 // d/RMAX
        unsigned mask = __ballot_sync(0xFFFFFFFFu, pred);
        while (mask) {
            int src = __ffs(mask) - 1;
            mask &= mask - 1;
            float ub  = __shfl_sync(0xFFFFFFFFu, u, src);   // warp-uniform
            float ub2 = ub * ub;
            if (ub < 3.2f + ZC) {         // low half (bins 1..32) alive
                float arg = fmaf(c2, ub2, fmaf(c1a, ub, c0a));
                acc1 = fmaf(exp2f(arg), w1, acc1);
            }
            if (ub > 3.3f - ZC) {         // high half (bins 33..50) alive
                float arg = fmaf(c2, ub2, fmaf(c1b, ub, c0b));
                acc2 = fmaf(exp2f(arg), w2, acc2);
            }
        }
    }

    // ---- Block reduction -> global ----
    atomicAdd(&sacc[lane], acc1);
    if (lane < NBINS - 32) atomicAdd(&sacc[lane + 32], acc2);
    __syncthreads();
    if (tid < NBINS) atomicAdd(&g_acc[tid], sacc[tid]);

    // ---- Last block finalizes ----
    __threadfence();
    if (tid == 0) {
        int v = atomicAdd(&g_done, 1);
        is_last = (v == NBLK - 1);
    }
    __syncthreads();
    if (is_last) {
        if (tid < NBINS) {
            int b = tid;
            double rs_d  = (b + 1) * (5.0 / 50.0) * RMAX_D;
            double inner = fmax(0.0, rs_d - 0.5 * RMAX_D);
            double outer = rs_d + 0.5 * RMAX_D;
            float  area  = (float)(M_PI * (outer * outer - inner * inner));
            const float GF = (float)(1.0 / (sqrt(M_PI) * 0.25));

            float s   = g_acc[b] * GF;
            float pcf = s / 1536.0f / (area * 1536.0f);

            out[2 * b]     = (float)rs_d / (float)RMAX_D;
            out[2 * b + 1] = pcf;

            g_acc[b] = 0.0f;          // reset for next graph replay
        }
        if (tid == 0) g_done = 0;
    }
}

// ---------------------------------------------------------------------------
extern "C" void kernel_launch(void* const* d_in, const int* in_sizes, int n_in,
                              void* d_out, int out_size)
{
    const float* A  = (const float*)d_in[0];   // disks_a [1536,3]
    const float* B  = (const float*)d_in[1];   // disks_b [1536,3]
    const int*   sc = (const int*)d_in[2];     // same_category scalar
    float* out = (float*)d_out;

    pcf_kernel<<<NBLK, NTHR>>>(A, B, sc, out);
}

// round 9
// speedup vs baseline: 1.3518x; 1.2237x over previous
#include <cuda_runtime.h>
#include <math.h>

// ---------------------------------------------------------------------------
// PrettyPCF, R8 (resubmit after infra failure): warp-per-i + per-warp
// compacted queue + polynomial math.
//  * Warp owns one i-point and a 512-long j-slice (JSPLIT=3 -> 576 blocks).
//  * Phase A: lanes test 32 j's; ballot + popc-prefix compact survivors'
//    u=d/RMAX into a warp-PRIVATE smem buffer (no atomics, no ffs loop).
//  * Phase B: counted drain, 2-way unroll, LDS broadcast, branchless
//    both-halves Gaussian: exp(-16(zb-u)^2) = ex2(c0[lane]+c1[lane]u+c2u^2).
//  * Weights in registers (lane l: bins l, l+32), via branchless polynomial
//    acos (A&S 4.4.45) / first-quadrant atan2; acos(1)=0 makes the rs>ex
//    guard automatic. No libm, no divergence.
// ---------------------------------------------------------------------------

#define NPTS   1536
#define NBINS  50
#define WPB    8                   // warps (== i-points) per block
#define NTHR   (WPB * 32)          // 256
#define ITILES (NPTS / WPB)        // 192
#define JSPLIT 3
#define JLEN   (NPTS / JSPLIT)     // 512
#define JITERS (JLEN / 32)         // 16
#define NBLK   (ITILES * JSPLIT)   // 576
#define QW     JLEN                // per-warp queue capacity (worst case)
#define ZC     1.2f

#define RMAX_D (2.0 * sqrt(1.0 / (2.0 * sqrt(3.0) * 1536.0)))

__device__ float g_acc[NBINS];   // zero-init at load; reset by last block
__device__ int   g_done;

__device__ __forceinline__ float ex2_fast(float x) {
    float y;
    asm("ex2.approx.ftz.f32 %0, %1;" : "=f"(y) : "f"(x));
    return y;
}

// acos(x), x in [0,1]; abs err < 6.7e-5 (A&S 4.4.45). acos(1) = 0 exactly.
__device__ __forceinline__ float acos_poly(float x) {
    float p = fmaf(x, fmaf(x, fmaf(x, -0.0187293f, 0.0742610f),
                               -0.2121144f), 1.5707288f);
    return sqrtf(1.0f - x) * p;
}

// atan(r), r in [0,1]; minimax odd poly, abs err ~1e-6.
__device__ __forceinline__ float atan_poly(float r) {
    float r2 = r * r;
    float p = fmaf(r2, fmaf(r2, fmaf(r2, fmaf(r2, fmaf(r2,
              -0.0117212f, 0.05265332f), -0.11643287f),
               0.19354346f), -0.33262347f), 0.99997726f);
    return r * p;
}

// atan2(y, x) for x,y >= 0 (first quadrant), branchless.
__device__ __forceinline__ float atan2_q1(float y, float x) {
    float mn = fminf(x, y);
    float mx = fmaxf(x, y);
    float r  = mn / fmaxf(mx, 1e-20f);
    float a  = atan_poly(r);
    return (y > x) ? (1.5707963268f - a) : a;
}

__global__ __launch_bounds__(NTHR)
void pcf_kernel(const float* __restrict__ A, const float* __restrict__ B,
                const int* __restrict__ scp, float* __restrict__ out)
{
    __shared__ float sbx[JLEN];
    __shared__ float sby[JLEN];
    __shared__ float swq[WPB * QW];      // per-warp survivor u's
    __shared__ float sacc[NBINS];
    __shared__ int   is_last;

    const int tid   = threadIdx.x;
    const int lane  = tid & 31;
    const int wid   = tid >> 5;
    const int itile = blockIdx.x % ITILES;
    const int jsp   = blockIdx.x / ITILES;
    const int i0    = itile * WPB;
    const int j0    = jsp * JLEN;
    const int i     = i0 + wid;          // this warp's i-point
    float* wq = &swq[wid * QW];

    // ---- Stage this block's B slice ----
    for (int t = tid; t < JLEN; t += NTHR) {
        sbx[t] = B[3 * (j0 + t)];
        sby[t] = B[3 * (j0 + t) + 1];
    }
    if (tid < NBINS) sacc[tid] = 0.0f;

    // ---- This warp's i coords (broadcast LDG) ----
    const float ax = A[3 * i];
    const float ay = A[3 * i + 1];

    // ---- Edge terms (all lanes redundantly, branchless) ----
    const float TWO_PI = 6.2831853071795864769f;
    const float ex0 = ax,        ey0 = ay;
    const float ex1 = 1.0f - ax, ey1 = ay;
    const float ex2v = ay,       ey2 = ax;
    const float ex3 = 1.0f - ay, ey3 = ax;
    const float a10 = atan2_q1(ey0,        ex0);
    const float a20 = atan2_q1(1.0f - ey0, ex0);
    const float a11 = atan2_q1(ey1,        ex1);
    const float a21 = atan2_q1(1.0f - ey1, ex1);
    const float a12 = atan2_q1(ey2,        ex2v);
    const float a22 = atan2_q1(1.0f - ey2, ex2v);
    const float a13 = atan2_q1(ey3,        ex3);
    const float a23 = atan2_q1(1.0f - ey3, ex3);

    // ---- Per-lane weights for bins lane (rs1) and lane+32 (rs2) ----
    // acos(min(ex/rs,1)) = 0 when rs<=ex, so the rs>ex guard is automatic
    // (contribution min(0,a1)+min(0,a2)=0 since a1,a2>=0). Fully branchless.
    const float rs1 = (float)((lane +  1) * (5.0 / 50.0) * RMAX_D);
    const float rs2 = (float)((lane + 33) * (5.0 / 50.0) * RMAX_D);

    float w1, w2;
    {
        float ir = 1.0f / rs1;
        float al0 = acos_poly(fminf(ex0  * ir, 1.0f));
        float al1 = acos_poly(fminf(ex1  * ir, 1.0f));
        float al2 = acos_poly(fminf(ex2v * ir, 1.0f));
        float al3 = acos_poly(fminf(ex3  * ir, 1.0f));
        float full = TWO_PI
            - (fminf(al0, a10) + fminf(al0, a20))
            - (fminf(al1, a11) + fminf(al1, a21))
            - (fminf(al2, a12) + fminf(al2, a22))
            - (fminf(al3, a13) + fminf(al3, a23));
        float per = fminf(fmaxf(full * (1.0f / TWO_PI), 0.0f), 1.0f);
        w1 = fminf(1.0f / fmaxf(per, 1e-9f), 4.0f);
    }
    {
        float ir = 1.0f / rs2;
        float al0 = acos_poly(fminf(ex0  * ir, 1.0f));
        float al1 = acos_poly(fminf(ex1  * ir, 1.0f));
        float al2 = acos_poly(fminf(ex2v * ir, 1.0f));
        float al3 = acos_poly(fminf(ex3  * ir, 1.0f));
        float full = TWO_PI
            - (fminf(al0, a10) + fminf(al0, a20))
            - (fminf(al1, a11) + fminf(al1, a21))
            - (fminf(al2, a12) + fminf(al2, a22))
            - (fminf(al3, a13) + fminf(al3, a23));
        float per = fminf(fmaxf(full * (1.0f / TWO_PI), 0.0f), 1.0f);
        w2 = fminf(1.0f / fmaxf(per, 1e-9f), 4.0f);
        if (lane >= NBINS - 32) w2 = 0.0f;   // dead bins contribute 0
    }

    // ---- exp2 coefficients: exp(-16 (zb-u)^2) = ex2(c0 + c1 u + c2 u^2) ----
    const float L2E = 1.4426950408889634f;
    const float c2  = -16.0f * L2E;
    const float zb1 = 0.1f * (float)(lane + 1);
    const float zb2 = zb1 + 3.2f;
    const float c1a = 32.0f * zb1 * L2E;
    const float c0a = -16.0f * zb1 * zb1 * L2E;
    const float c1b = 32.0f * zb2 * L2E;
    const float c0b = -16.0f * zb2 * zb2 * L2E;

    const int   same = *scp;
    const float invR = (float)(1.0 / RMAX_D);
    const float dmax = (float)((5.0 + (double)ZC) * RMAX_D);
    const float cut2 = dmax * dmax;

    __syncthreads();   // sbx/sby + sacc ready

    // ---- Phase A: ballot + popc-prefix compaction into warp queue ----
    int cnt = 0;
    const unsigned lt_mask = (1u << lane) - 1u;
#pragma unroll 4
    for (int jt = 0; jt < JITERS; jt++) {
        int   jl = jt * 32 + lane;
        float bx = sbx[jl], by = sby[jl];
        float dx = ax - bx;
        float dy = ay - by;
        float d2 = fmaf(dx, dx, dy * dy);
        bool pred = (d2 < cut2) && !(same && i == (j0 + jl));
        unsigned mask = __ballot_sync(0xFFFFFFFFu, pred);
        if (pred) {
            int slot = cnt + __popc(mask & lt_mask);
            wq[slot] = sqrtf(d2) * invR;      // u = d/RMAX
        }
        cnt += __popc(mask);
    }
    __syncwarp();

    // ---- Phase B: counted drain, 2-way unroll, branchless both halves ----
    float acc1 = 0.0f, acc2 = 0.0f;
    int e = 0;
    for (; e + 1 < cnt; e += 2) {
        float uA  = wq[e];                    // LDS broadcast
        float uB  = wq[e + 1];
        float uA2 = uA * uA;
        float uB2 = uB * uB;
        float gA1 = ex2_fast(fmaf(c2, uA2, fmaf(c1a, uA, c0a)));
        float gB1 = ex2_fast(fmaf(c2, uB2, fmaf(c1a, uB, c0a)));
        float gA2 = ex2_fast(fmaf(c2, uA2, fmaf(c1b, uA, c0b)));
        float gB2 = ex2_fast(fmaf(c2, uB2, fmaf(c1b, uB, c0b)));
        acc1 = fmaf(gA1, w1, acc1);
        acc1 = fmaf(gB1, w1, acc1);
        acc2 = fmaf(gA2, w2, acc2);
        acc2 = fmaf(gB2, w2, acc2);
    }
    if (e < cnt) {
        float u  = wq[e];
        float u2 = u * u;
        acc1 = fmaf(ex2_fast(fmaf(c2, u2, fmaf(c1a, u, c0a))), w1, acc1);
        acc2 = fmaf(ex2_fast(fmaf(c2, u2, fmaf(c1b, u, c0b))), w2, acc2);
    }

    // ---- Block reduction -> global ----
    atomicAdd(&sacc[lane], acc1);
    if (lane < NBINS - 32) atomicAdd(&sacc[lane + 32], acc2);
    __syncthreads();
    if (tid < NBINS) atomicAdd(&g_acc[tid], sacc[tid]);

    // ---- Last block finalizes ----
    __threadfence();
    if (tid == 0) {
        int v = atomicAdd(&g_done, 1);
        is_last = (v == NBLK - 1);
    }
    __syncthreads();
    if (is_last) {
        if (tid < NBINS) {
            int b = tid;
            double rs_d  = (b + 1) * (5.0 / 50.0) * RMAX_D;
            double inner = fmax(0.0, rs_d - 0.5 * RMAX_D);
            double outer = rs_d + 0.5 * RMAX_D;
            float  area  = (float)(M_PI * (outer * outer - inner * inner));
            const float GF = (float)(1.0 / (sqrt(M_PI) * 0.25));

            float s   = g_acc[b] * GF;
            float pcf = s / 1536.0f / (area * 1536.0f);

            out[2 * b]     = (float)rs_d / (float)RMAX_D;
            out[2 * b + 1] = pcf;

            g_acc[b] = 0.0f;          // reset for next graph replay
        }
        if (tid == 0) g_done = 0;
    }
}

// ---------------------------------------------------------------------------
extern "C" void kernel_launch(void* const* d_in, const int* in_sizes, int n_in,
                              void* d_out, int out_size)
{
    const float* A  = (const float*)d_in[0];   // disks_a [1536,3]
    const float* B  = (const float*)d_in[1];   // disks_b [1536,3]
    const int*   sc = (const int*)d_in[2];     // same_category scalar
    float* out = (float*)d_out;

    pcf_kernel<<<NBLK, NTHR>>>(A, B, sc, out);
}